// round 9
// baseline (speedup 1.0000x reference)
#include <cuda_runtime.h>
#include <mma.h>
#include <cstdint>
#include <math.h>

using namespace nvcuda;

#define BATCH 2
#define SEQ   2048
#define EMB   1024
#define NHEAD 16
#define HDIM  64
#define E3    3072

#define OUT_ELEMS_C ((size_t)BATCH * SEQ * EMB)

// Scratch (__device__ globals per allocation rules)
__device__ float g_qkv [(size_t)BATCH * SEQ * E3];            // 50 MB
__device__ float g_ctx [(size_t)BATCH * SEQ * EMB];           // 16 MB
__device__ float g_ctxp[(size_t)4 * BATCH * SEQ * EMB];       // 64 MB split-K partials
__device__ float g_attn[(size_t)BATCH * NHEAD * SEQ * SEQ];   // 512 MB fallback

typedef wmma::fragment<wmma::matrix_a, 16, 16, 8, wmma::precision::tf32, wmma::row_major> FragA;
typedef wmma::fragment<wmma::matrix_b, 16, 16, 8, wmma::precision::tf32, wmma::row_major> FragBR;
typedef wmma::fragment<wmma::matrix_b, 16, 16, 8, wmma::precision::tf32, wmma::col_major> FragBC;
typedef wmma::fragment<wmma::accumulator, 16, 16, 8, float> FragC;

template<class F>
__device__ __forceinline__ void to_tf32(F& f) {
    #pragma unroll
    for (int i = 0; i < f.num_elements; i++) f.x[i] = wmma::__float_to_tf32(f.x[i]);
}

__device__ __forceinline__ void cpa16(float* s, const float* g) {
    uint32_t sa = (uint32_t)__cvta_generic_to_shared(s);
    asm volatile("cp.async.ca.shared.global [%0], [%1], 16;" :: "r"(sa), "l"(g));
}
#define CP_COMMIT() asm volatile("cp.async.commit_group;" ::: "memory")
#define CP_WAIT(n)  asm volatile("cp.async.wait_group %0;" :: "n"(n) : "memory")

// ---------------------------------------------------------------------------
// GEMM + bias: C[M,N] = A[M,K] @ B[K,N] + bias[N]
// BM=128, BN=128, BK=32, 256 threads, 3-stage cp.async, 2 CTAs/SM.
// ---------------------------------------------------------------------------
#define AS_STRIDE 36
#define BS_STRIDE 132
#define AS_BUF (128 * AS_STRIDE)
#define BS_BUF (32 * BS_STRIDE)
#define GSM (3 * (AS_BUF + BS_BUF) * 4)   // 105984 B

__device__ __forceinline__ void load_gemm_A(float* dst, const float* Ab,
                                            int lda, int tid) {
    const int ar = tid >> 1, ac = (tid & 1) * 16;
    const float* gp = Ab + (size_t)ar * lda + ac;
    float* sp = dst + ar * AS_STRIDE + ac;
    cpa16(sp + 0,  gp + 0);
    cpa16(sp + 4,  gp + 4);
    cpa16(sp + 8,  gp + 8);
    cpa16(sp + 12, gp + 12);
}
__device__ __forceinline__ void load_gemm_B(float* dst, const float* Bb,
                                            int ldb, int tid) {
    #pragma unroll
    for (int t = 0; t < 4; t++) {
        int idx = tid + t * 256;
        int r = idx >> 5, c = (idx & 31) * 4;
        cpa16(&dst[r * BS_STRIDE + c], &Bb[(size_t)r * ldb + c]);
    }
}

__global__ __launch_bounds__(256, 2) void gemm_bias_w(
    const float* __restrict__ A, const float* __restrict__ B,
    const float* __restrict__ bias, float* __restrict__ C, int K, int N)
{
    extern __shared__ float sm[];
    float* As = sm;                    // 3 x [128][36]
    float* Bs = sm + 3 * AS_BUF;       // 3 x [32][132]
    float* Cs = sm;                    // [128][132] (reused after mainloop)

    const int m0 = blockIdx.y * 128, n0 = blockIdx.x * 128;
    const int tid = threadIdx.x;
    const int w = tid >> 5;
    const int wr = w >> 1, wc = w & 1;

    FragC acc[2][4];
    #pragma unroll
    for (int i = 0; i < 2; i++)
        #pragma unroll
        for (int j = 0; j < 4; j++) wmma::fill_fragment(acc[i][j], 0.f);

    const int nk = K / 32;

    // Prologue: prefetch chunks 0 and 1
    load_gemm_A(As, A + (size_t)m0 * K, K, tid);
    load_gemm_B(Bs, B + n0, N, tid);
    CP_COMMIT();
    if (nk > 1) {
        load_gemm_A(As + AS_BUF, A + (size_t)m0 * K + 32, K, tid);
        load_gemm_B(Bs + BS_BUF, B + (size_t)32 * N + n0, N, tid);
        CP_COMMIT();
    }

    for (int kt = 0; kt < nk; kt++) {
        if (kt + 2 < nk) {
            const int st = (kt + 2) % 3;
            const int k0 = (kt + 2) * 32;
            load_gemm_A(As + st * AS_BUF, A + (size_t)m0 * K + k0, K, tid);
            load_gemm_B(Bs + st * BS_BUF, B + (size_t)k0 * N + n0, N, tid);
            CP_COMMIT();
            CP_WAIT(2);
        } else if (kt + 1 < nk) {
            CP_WAIT(1);
        } else {
            CP_WAIT(0);
        }
        __syncthreads();

        const float* Ac = As + (kt % 3) * AS_BUF;
        const float* Bc = Bs + (kt % 3) * BS_BUF;
        #pragma unroll
        for (int kk = 0; kk < 32; kk += 8) {
            FragA a[2];
            FragBR b[4];
            #pragma unroll
            for (int i = 0; i < 2; i++) {
                wmma::load_matrix_sync(a[i], &Ac[(wr * 32 + i * 16) * AS_STRIDE + kk], AS_STRIDE);
                to_tf32(a[i]);
            }
            #pragma unroll
            for (int j = 0; j < 4; j++) {
                wmma::load_matrix_sync(b[j], &Bc[kk * BS_STRIDE + wc * 64 + j * 16], BS_STRIDE);
                to_tf32(b[j]);
            }
            #pragma unroll
            for (int i = 0; i < 2; i++)
                #pragma unroll
                for (int j = 0; j < 4; j++)
                    wmma::mma_sync(acc[i][j], a[i], b[j], acc[i][j]);
        }
        __syncthreads();
    }

    #pragma unroll
    for (int i = 0; i < 2; i++)
        #pragma unroll
        for (int j = 0; j < 4; j++)
            wmma::store_matrix_sync(&Cs[(wr * 32 + i * 16) * BS_STRIDE + wc * 64 + j * 16],
                                    acc[i][j], BS_STRIDE, wmma::mem_row_major);
    __syncthreads();
    #pragma unroll
    for (int t = 0; t < 16; t++) {
        int idx = tid + t * 256;
        int r = idx >> 5, c = (idx & 31) * 4;
        float4 v = *(float4*)&Cs[r * BS_STRIDE + c];
        const float* bp = bias + n0 + c;
        v.x += bp[0]; v.y += bp[1]; v.z += bp[2]; v.w += bp[3];
        *(float4*)&C[(size_t)(m0 + r) * N + n0 + c] = v;
    }
}

// ---------------------------------------------------------------------------
// Scores: attn[bh,i,j] = (Q_i . K_j)/8 + slope(h)*(j-i).  grid(16,16,32)
// ---------------------------------------------------------------------------
#define QK_STRIDE 68
#define SSM (2 * 128 * QK_STRIDE * 4)   // 69632 B (Cs 128x132 reuses prefix)

__global__ __launch_bounds__(256, 2) void scores_w(
    const float* __restrict__ qkv, float* __restrict__ attn)
{
    extern __shared__ float sm[];
    float* Qs = sm;                      // [128][68]
    float* Ks = sm + 128 * QK_STRIDE;    // [128][68]
    float* Cs = sm;                      // [128][132] (reused)

    const int bh = blockIdx.z, b = bh >> 4, h = bh & 15;
    const int i0 = blockIdx.y * 128, j0 = blockIdx.x * 128;
    const float* Qg = qkv + (size_t)b * SEQ * E3 + h * 192;
    const float* Kg = qkv + (size_t)b * SEQ * E3 + h * 192 + 64;

    const int tid = threadIdx.x;
    const int w = tid >> 5;
    const int wr = w >> 1, wc = w & 1;

    #pragma unroll
    for (int t = 0; t < 8; t++) {
        int idx = tid + t * 256;
        int r = idx >> 4, c = (idx & 15) * 4;
        cpa16(&Qs[r * QK_STRIDE + c], &Qg[(size_t)(i0 + r) * E3 + c]);
        cpa16(&Ks[r * QK_STRIDE + c], &Kg[(size_t)(j0 + r) * E3 + c]);
    }
    CP_COMMIT();
    CP_WAIT(0);
    __syncthreads();

    FragC acc[2][4];
    #pragma unroll
    for (int i = 0; i < 2; i++)
        #pragma unroll
        for (int j = 0; j < 4; j++) wmma::fill_fragment(acc[i][j], 0.f);

    #pragma unroll
    for (int kk = 0; kk < 64; kk += 8) {
        FragA a[2];
        FragBC bf[4];
        #pragma unroll
        for (int i = 0; i < 2; i++) {
            wmma::load_matrix_sync(a[i], &Qs[(wr * 32 + i * 16) * QK_STRIDE + kk], QK_STRIDE);
            to_tf32(a[i]);
        }
        #pragma unroll
        for (int j = 0; j < 4; j++) {
            wmma::load_matrix_sync(bf[j], &Ks[(wc * 64 + j * 16) * QK_STRIDE + kk], QK_STRIDE);
            to_tf32(bf[j]);
        }
        #pragma unroll
        for (int i = 0; i < 2; i++)
            #pragma unroll
            for (int j = 0; j < 4; j++)
                wmma::mma_sync(acc[i][j], a[i], bf[j], acc[i][j]);
    }
    __syncthreads();

    #pragma unroll
    for (int i = 0; i < 2; i++)
        #pragma unroll
        for (int j = 0; j < 4; j++)
            wmma::store_matrix_sync(&Cs[(wr * 32 + i * 16) * 132 + wc * 64 + j * 16],
                                    acc[i][j], 132, wmma::mem_row_major);
    __syncthreads();

    const float slope = exp2f(-0.5f * (float)(h + 1));
    #pragma unroll
    for (int t = 0; t < 16; t++) {
        int idx = tid + t * 256;
        int r = idx >> 5, c = (idx & 31) * 4;
        const int gi = i0 + r, gj = j0 + c;
        float4 v = *(float4*)&Cs[r * 132 + c];
        v.x = v.x * 0.125f + slope * (float)(gj + 0 - gi);
        v.y = v.y * 0.125f + slope * (float)(gj + 1 - gi);
        v.z = v.z * 0.125f + slope * (float)(gj + 2 - gi);
        v.w = v.w * 0.125f + slope * (float)(gj + 3 - gi);
        *(float4*)&attn[((size_t)bh * SEQ + gi) * SEQ + gj] = v;
    }
}

// ---------------------------------------------------------------------------
// AV split-K x4: ctxp[q4][b,q,h*64+d] = sum_{k in quarter} attn[bh,q,k]*V[k,d]
// grid(16, 4, 32). BM=128, BN=64, BK=32, 3-stage cp.async.
// ---------------------------------------------------------------------------
#define AVA_BUF (128 * 36)
#define AVV_BUF (32 * 68)
#define AVSM (3 * (AVA_BUF + AVV_BUF) * 4)   // 81408 B

__device__ __forceinline__ void load_av_A(float* dst, const float* Ab, int tid) {
    const int ar = tid >> 1, ac = (tid & 1) * 16;
    const float* gp = Ab + (size_t)ar * SEQ + ac;
    float* sp = dst + ar * 36 + ac;
    cpa16(sp + 0,  gp + 0);
    cpa16(sp + 4,  gp + 4);
    cpa16(sp + 8,  gp + 8);
    cpa16(sp + 12, gp + 12);
}
__device__ __forceinline__ void load_av_V(float* dst, const float* Vb, int tid) {
    const int vr = tid >> 4, vc = (tid & 15) * 4;
    cpa16(&dst[vr * 68 + vc],        &Vb[(size_t)vr * E3 + vc]);
    cpa16(&dst[(vr + 16) * 68 + vc], &Vb[(size_t)(vr + 16) * E3 + vc]);
}

__global__ __launch_bounds__(256, 2) void av_w(
    const float* __restrict__ attn, const float* __restrict__ qkv,
    float* __restrict__ ctxp)
{
    extern __shared__ float sm[];
    float* As = sm;                    // 3 x [128][36]
    float* Vs = sm + 3 * AVA_BUF;      // 3 x [32][68]

    const int bh = blockIdx.z, b = bh >> 4, h = bh & 15;
    const int i0 = blockIdx.x * 128;
    const int quarter = blockIdx.y;
    const int kbase = quarter * (SEQ / 4);
    float* ctx = ctxp + (size_t)quarter * OUT_ELEMS_C;

    const float* Ag = attn + ((size_t)bh * SEQ + i0) * SEQ + kbase;
    const float* Vg = qkv + (size_t)b * SEQ * E3 + (size_t)kbase * E3 + h * 192 + 128;

    const int tid = threadIdx.x;
    const int w = tid >> 5;
    const int wr = w >> 1, wc = w & 1;

    FragC acc[2][2];
    #pragma unroll
    for (int i = 0; i < 2; i++)
        #pragma unroll
        for (int j = 0; j < 2; j++) wmma::fill_fragment(acc[i][j], 0.f);

    const int nk = (SEQ / 4) / 32;  // 16

    load_av_A(As, Ag, tid);
    load_av_V(Vs, Vg, tid);
    CP_COMMIT();
    load_av_A(As + AVA_BUF, Ag + 32, tid);
    load_av_V(Vs + AVV_BUF, Vg + (size_t)32 * E3, tid);
    CP_COMMIT();

    for (int kt = 0; kt < nk; kt++) {
        if (kt + 2 < nk) {
            const int st = (kt + 2) % 3;
            const int k0 = (kt + 2) * 32;
            load_av_A(As + st * AVA_BUF, Ag + k0, tid);
            load_av_V(Vs + st * AVV_BUF, Vg + (size_t)k0 * E3, tid);
            CP_COMMIT();
            CP_WAIT(2);
        } else if (kt + 1 < nk) {
            CP_WAIT(1);
        } else {
            CP_WAIT(0);
        }
        __syncthreads();

        const float* Ac = As + (kt % 3) * AVA_BUF;
        const float* Vc = Vs + (kt % 3) * AVV_BUF;
        #pragma unroll
        for (int kk = 0; kk < 32; kk += 8) {
            FragA a[2];
            FragBR bf[2];
            #pragma unroll
            for (int i = 0; i < 2; i++) {
                wmma::load_matrix_sync(a[i], &Ac[(wr * 32 + i * 16) * 36 + kk], 36);
                to_tf32(a[i]);
            }
            #pragma unroll
            for (int j = 0; j < 2; j++) {
                wmma::load_matrix_sync(bf[j], &Vc[kk * 68 + wc * 32 + j * 16], 68);
                to_tf32(bf[j]);
            }
            #pragma unroll
            for (int i = 0; i < 2; i++)
                #pragma unroll
                for (int j = 0; j < 2; j++)
                    wmma::mma_sync(acc[i][j], a[i], bf[j], acc[i][j]);
        }
        __syncthreads();
    }

    #pragma unroll
    for (int i = 0; i < 2; i++) {
        const int q = i0 + wr * 32 + i * 16;
        #pragma unroll
        for (int j = 0; j < 2; j++)
            wmma::store_matrix_sync(
                &ctx[((size_t)(b * SEQ + q)) * EMB + h * HDIM + wc * 32 + j * 16],
                acc[i][j], EMB, wmma::mem_row_major);
    }
}

// ---------------------------------------------------------------------------
// Combine split-K partials: ctx = sum of 4 partials (float4)
// ---------------------------------------------------------------------------
__global__ __launch_bounds__(256) void combine_ctx(
    const float* __restrict__ cp, float* __restrict__ ctx)
{
    const size_t i = ((size_t)blockIdx.x * 256 + threadIdx.x) * 4;
    float4 a = *(const float4*)(cp + i);
    float4 b = *(const float4*)(cp + OUT_ELEMS_C + i);
    float4 c = *(const float4*)(cp + 2 * OUT_ELEMS_C + i);
    float4 d = *(const float4*)(cp + 3 * OUT_ELEMS_C + i);
    a.x += b.x + c.x + d.x;
    a.y += b.y + c.y + d.y;
    a.z += b.z + c.z + d.z;
    a.w += b.w + c.w + d.w;
    *(float4*)(ctx + i) = a;
}

// ---------------------------------------------------------------------------
// Row softmax over last dim (S=2048), in place. One block (256 thr) per row.
// ---------------------------------------------------------------------------
__global__ __launch_bounds__(256) void softmax_kernel(float* __restrict__ attn)
{
    float* p = attn + (size_t)blockIdx.x * SEQ;
    const int tid = threadIdx.x;
    float4 a = ((const float4*)p)[tid];
    float4 b = ((const float4*)p)[tid + 256];

    float m = fmaxf(fmaxf(fmaxf(a.x, a.y), fmaxf(a.z, a.w)),
                    fmaxf(fmaxf(b.x, b.y), fmaxf(b.z, b.w)));
    #pragma unroll
    for (int o = 16; o > 0; o >>= 1)
        m = fmaxf(m, __shfl_xor_sync(0xffffffffu, m, o));

    __shared__ float sm_[8], ss[8];
    if ((tid & 31) == 0) sm_[tid >> 5] = m;
    __syncthreads();
    m = sm_[0];
    #pragma unroll
    for (int w = 1; w < 8; w++) m = fmaxf(m, sm_[w]);

    a.x = expf(a.x - m); a.y = expf(a.y - m); a.z = expf(a.z - m); a.w = expf(a.w - m);
    b.x = expf(b.x - m); b.y = expf(b.y - m); b.z = expf(b.z - m); b.w = expf(b.w - m);

    float s = a.x + a.y + a.z + a.w + b.x + b.y + b.z + b.w;
    #pragma unroll
    for (int o = 16; o > 0; o >>= 1)
        s += __shfl_xor_sync(0xffffffffu, s, o);
    if ((tid & 31) == 0) ss[tid >> 5] = s;
    __syncthreads();
    s = ss[0];
    #pragma unroll
    for (int w = 1; w < 8; w++) s += ss[w];

    const float inv = 1.0f / s;
    a.x *= inv; a.y *= inv; a.z *= inv; a.w *= inv;
    b.x *= inv; b.y *= inv; b.z *= inv; b.w *= inv;
    ((float4*)p)[tid]       = a;
    ((float4*)p)[tid + 256] = b;
}

// ---------------------------------------------------------------------------
extern "C" void kernel_launch(void* const* d_in, const int* in_sizes, int n_in,
                              void* d_out, int out_size)
{
    const float* x    = (const float*)d_in[0];
    const float* Wqkv = (const float*)d_in[1];
    const float* bqkv = (const float*)d_in[2];
    const float* Wout = (const float*)d_in[3];
    const float* bout = (const float*)d_in[4];
    float* out = (float*)d_out;

    const long long OUT_ELEMS  = (long long)BATCH * SEQ * EMB;
    const long long ATTN_ELEMS = (long long)BATCH * NHEAD * SEQ * SEQ;

    float *qkv, *ctx, *ctxp, *attn;
    cudaGetSymbolAddress((void**)&qkv,  g_qkv);
    cudaGetSymbolAddress((void**)&ctx,  g_ctx);
    cudaGetSymbolAddress((void**)&ctxp, g_ctxp);
    if ((long long)out_size >= OUT_ELEMS + ATTN_ELEMS) {
        attn = out + OUT_ELEMS;
    } else {
        cudaGetSymbolAddress((void**)&attn, g_attn);
    }

    cudaFuncSetAttribute(gemm_bias_w, cudaFuncAttributeMaxDynamicSharedMemorySize, GSM);
    cudaFuncSetAttribute(scores_w,    cudaFuncAttributeMaxDynamicSharedMemorySize, SSM);
    cudaFuncSetAttribute(av_w,        cudaFuncAttributeMaxDynamicSharedMemorySize, AVSM);

    const int M = BATCH * SEQ;  // 4096

    // 1) QKV projection
    gemm_bias_w<<<dim3(E3 / 128, M / 128), 256, GSM>>>(x, Wqkv, bqkv, qkv, EMB, E3);

    // 2) Scores + ALiBi
    scores_w<<<dim3(SEQ / 128, SEQ / 128, BATCH * NHEAD), 256, SSM>>>(qkv, attn);

    // 3) Softmax
    softmax_kernel<<<BATCH * NHEAD * SEQ, 256>>>(attn);

    // 4) AV (split-K x4) + combine
    av_w<<<dim3(SEQ / 128, 4, BATCH * NHEAD), 256, AVSM>>>(attn, qkv, ctxp);
    combine_ctx<<<(int)(OUT_ELEMS / 4 / 256), 256>>>(ctxp, ctx);

    // 5) Output projection
    gemm_bias_w<<<dim3(EMB / 128, M / 128), 256, GSM>>>(ctx, Wout, bout, out, EMB, EMB);
}

// round 10
// speedup vs baseline: 1.1024x; 1.1024x over previous
#include <cuda_runtime.h>
#include <mma.h>
#include <cstdint>
#include <math.h>

using namespace nvcuda;

#define BATCH 2
#define SEQ   2048
#define EMB   1024
#define NHEAD 16
#define HDIM  64
#define E3    3072

// Scratch (__device__ globals per allocation rules)
__device__ float g_qkv  [(size_t)BATCH * SEQ * E3];            // 50 MB
__device__ float g_ctx  [(size_t)BATCH * SEQ * EMB];           // 16 MB
__device__ float g_ctx0 [(size_t)BATCH * SEQ * EMB];           // 16 MB partial
__device__ float g_ctx1 [(size_t)BATCH * SEQ * EMB];           // 16 MB partial
__device__ float g_attn [(size_t)BATCH * NHEAD * SEQ * SEQ];   // 512 MB fallback

typedef wmma::fragment<wmma::matrix_a, 16, 16, 8, wmma::precision::tf32, wmma::row_major> FragA;
typedef wmma::fragment<wmma::matrix_b, 16, 16, 8, wmma::precision::tf32, wmma::row_major> FragBR;
typedef wmma::fragment<wmma::matrix_b, 16, 16, 8, wmma::precision::tf32, wmma::col_major> FragBC;
typedef wmma::fragment<wmma::accumulator, 16, 16, 8, float> FragC;

template<class F>
__device__ __forceinline__ void to_tf32(F& f) {
    #pragma unroll
    for (int i = 0; i < f.num_elements; i++) f.x[i] = wmma::__float_to_tf32(f.x[i]);
}

__device__ __forceinline__ void cpa16(float* s, const float* g) {
    uint32_t sa = (uint32_t)__cvta_generic_to_shared(s);
    asm volatile("cp.async.ca.shared.global [%0], [%1], 16;" :: "r"(sa), "l"(g));
}
#define CP_COMMIT() asm volatile("cp.async.commit_group;" ::: "memory")
#define CP_WAIT(n)  asm volatile("cp.async.wait_group %0;" :: "n"(n) : "memory")

// ---------------------------------------------------------------------------
// GEMM + bias: C[M,N] = A[M,K] @ B[K,N] + bias[N]
// BM=128, BN=128, BK=32, 256 threads, 2-stage cp.async, 2 CTAs/SM. (R8)
// ---------------------------------------------------------------------------
#define AS_STRIDE 36
#define BS_STRIDE 132
#define AS_BUF (128 * AS_STRIDE)
#define BS_BUF (32 * BS_STRIDE)
#define GSM ((2 * AS_BUF + 2 * BS_BUF) * 4)   // 70656 B

__device__ __forceinline__ void load_gemm_A(float* dst, const float* Ab,
                                            int lda, int tid) {
    const int ar = tid >> 1, ac = (tid & 1) * 16;
    const float* gp = Ab + (size_t)ar * lda + ac;
    float* sp = dst + ar * AS_STRIDE + ac;
    cpa16(sp + 0,  gp + 0);
    cpa16(sp + 4,  gp + 4);
    cpa16(sp + 8,  gp + 8);
    cpa16(sp + 12, gp + 12);
}
__device__ __forceinline__ void load_gemm_B(float* dst, const float* Bb,
                                            int ldb, int tid) {
    #pragma unroll
    for (int t = 0; t < 4; t++) {
        int idx = tid + t * 256;
        int r = idx >> 5, c = (idx & 31) * 4;
        cpa16(&dst[r * BS_STRIDE + c], &Bb[(size_t)r * ldb + c]);
    }
}

__global__ __launch_bounds__(256, 2) void gemm_bias_w(
    const float* __restrict__ A, const float* __restrict__ B,
    const float* __restrict__ bias, float* __restrict__ C, int K, int N)
{
    extern __shared__ float sm[];
    float* As = sm;
    float* Bs = sm + 2 * AS_BUF;
    float* Cs = sm;   // reused after mainloop

    const int m0 = blockIdx.y * 128, n0 = blockIdx.x * 128;
    const int tid = threadIdx.x;
    const int w = tid >> 5;
    const int wr = w >> 1, wc = w & 1;

    FragC acc[2][4];
    #pragma unroll
    for (int i = 0; i < 2; i++)
        #pragma unroll
        for (int j = 0; j < 4; j++) wmma::fill_fragment(acc[i][j], 0.f);

    const int nk = K / 32;
    load_gemm_A(As, A + (size_t)m0 * K, K, tid);
    load_gemm_B(Bs, B + n0, N, tid);
    CP_COMMIT();

    for (int kt = 0; kt < nk; kt++) {
        const int cur = kt & 1;
        if (kt + 1 < nk) {
            const int k0 = (kt + 1) * 32;
            load_gemm_A(As + (cur ^ 1) * AS_BUF, A + (size_t)m0 * K + k0, K, tid);
            load_gemm_B(Bs + (cur ^ 1) * BS_BUF, B + (size_t)k0 * N + n0, N, tid);
            CP_COMMIT();
            CP_WAIT(1);
        } else {
            CP_WAIT(0);
        }
        __syncthreads();

        const float* Ac = As + cur * AS_BUF;
        const float* Bc = Bs + cur * BS_BUF;
        #pragma unroll
        for (int kk = 0; kk < 32; kk += 8) {
            FragA a[2];
            FragBR b[4];
            #pragma unroll
            for (int i = 0; i < 2; i++) {
                wmma::load_matrix_sync(a[i], &Ac[(wr * 32 + i * 16) * AS_STRIDE + kk], AS_STRIDE);
                to_tf32(a[i]);
            }
            #pragma unroll
            for (int j = 0; j < 4; j++) {
                wmma::load_matrix_sync(b[j], &Bc[kk * BS_STRIDE + wc * 64 + j * 16], BS_STRIDE);
                to_tf32(b[j]);
            }
            #pragma unroll
            for (int i = 0; i < 2; i++)
                #pragma unroll
                for (int j = 0; j < 4; j++)
                    wmma::mma_sync(acc[i][j], a[i], b[j], acc[i][j]);
        }
        __syncthreads();
    }

    #pragma unroll
    for (int i = 0; i < 2; i++)
        #pragma unroll
        for (int j = 0; j < 4; j++)
            wmma::store_matrix_sync(&Cs[(wr * 32 + i * 16) * BS_STRIDE + wc * 64 + j * 16],
                                    acc[i][j], BS_STRIDE, wmma::mem_row_major);
    __syncthreads();
    #pragma unroll
    for (int t = 0; t < 16; t++) {
        int idx = tid + t * 256;
        int r = idx >> 5, c = (idx & 31) * 4;
        float4 v = *(float4*)&Cs[r * BS_STRIDE + c];
        const float* bp = bias + n0 + c;
        v.x += bp[0]; v.y += bp[1]; v.z += bp[2]; v.w += bp[3];
        *(float4*)&C[(size_t)(m0 + r) * N + n0 + c] = v;
    }
}

// ---------------------------------------------------------------------------
// Scores: attn[bh,i,j] = Q_i . K_j  (RAW — scale/ALiBi applied in softmax)
// grid(16,16,32). Fragments stored directly to global, no epilogue staging.
// ---------------------------------------------------------------------------
#define QK_STRIDE 68
#define SSM (2 * 128 * QK_STRIDE * 4)   // 69632 B

__global__ __launch_bounds__(256, 2) void scores_w(
    const float* __restrict__ qkv, float* __restrict__ attn)
{
    extern __shared__ float sm[];
    float* Qs = sm;                      // [128][68]
    float* Ks = sm + 128 * QK_STRIDE;    // [128][68]

    const int bh = blockIdx.z, b = bh >> 4, h = bh & 15;
    const int i0 = blockIdx.y * 128, j0 = blockIdx.x * 128;
    const float* Qg = qkv + (size_t)b * SEQ * E3 + h * 192;
    const float* Kg = qkv + (size_t)b * SEQ * E3 + h * 192 + 64;

    const int tid = threadIdx.x;
    const int w = tid >> 5;
    const int wr = w >> 1, wc = w & 1;

    #pragma unroll
    for (int t = 0; t < 8; t++) {
        int idx = tid + t * 256;
        int r = idx >> 4, c = (idx & 15) * 4;
        cpa16(&Qs[r * QK_STRIDE + c], &Qg[(size_t)(i0 + r) * E3 + c]);
        cpa16(&Ks[r * QK_STRIDE + c], &Kg[(size_t)(j0 + r) * E3 + c]);
    }
    CP_COMMIT();
    CP_WAIT(0);
    __syncthreads();

    FragC acc[2][4];
    #pragma unroll
    for (int i = 0; i < 2; i++)
        #pragma unroll
        for (int j = 0; j < 4; j++) wmma::fill_fragment(acc[i][j], 0.f);

    #pragma unroll
    for (int kk = 0; kk < 64; kk += 8) {
        FragA a[2];
        FragBC bf[4];
        #pragma unroll
        for (int i = 0; i < 2; i++) {
            wmma::load_matrix_sync(a[i], &Qs[(wr * 32 + i * 16) * QK_STRIDE + kk], QK_STRIDE);
            to_tf32(a[i]);
        }
        #pragma unroll
        for (int j = 0; j < 4; j++) {
            wmma::load_matrix_sync(bf[j], &Ks[(wc * 64 + j * 16) * QK_STRIDE + kk], QK_STRIDE);
            to_tf32(bf[j]);
        }
        #pragma unroll
        for (int i = 0; i < 2; i++)
            #pragma unroll
            for (int j = 0; j < 4; j++)
                wmma::mma_sync(acc[i][j], a[i], bf[j], acc[i][j]);
    }

    // Direct fragment stores to global (raw scores)
    float* Abase = attn + ((size_t)bh * SEQ + i0) * SEQ + j0;
    #pragma unroll
    for (int i = 0; i < 2; i++)
        #pragma unroll
        for (int j = 0; j < 4; j++)
            wmma::store_matrix_sync(
                &Abase[(size_t)(wr * 32 + i * 16) * SEQ + wc * 64 + j * 16],
                acc[i][j], SEQ, wmma::mem_row_major);
}

// ---------------------------------------------------------------------------
// Softmax with fused scale + ALiBi. attn holds raw QK^T on entry,
// probabilities on exit. One block (256 thr) per row.
// ---------------------------------------------------------------------------
__global__ __launch_bounds__(256) void softmax_kernel(float* __restrict__ attn)
{
    const int row = blockIdx.x;              // bh*2048 + i
    const int i = row & (SEQ - 1);
    const int h = (row >> 11) & (NHEAD - 1);
    const float slope = exp2f(-0.5f * (float)(h + 1));

    float* p = attn + (size_t)row * SEQ;
    const int tid = threadIdx.x;

    float4 a = ((const float4*)p)[tid];
    float4 b = ((const float4*)p)[tid + 256];

    // scale + ALiBi: v*0.125 + slope*(j - i)
    {
        const float base_a = slope * (float)(tid * 4 - i);
        a.x = a.x * 0.125f + base_a;
        a.y = a.y * 0.125f + base_a + slope;
        a.z = a.z * 0.125f + base_a + 2.f * slope;
        a.w = a.w * 0.125f + base_a + 3.f * slope;
        const float base_b = slope * (float)((tid + 256) * 4 - i);
        b.x = b.x * 0.125f + base_b;
        b.y = b.y * 0.125f + base_b + slope;
        b.z = b.z * 0.125f + base_b + 2.f * slope;
        b.w = b.w * 0.125f + base_b + 3.f * slope;
    }

    float m = fmaxf(fmaxf(fmaxf(a.x, a.y), fmaxf(a.z, a.w)),
                    fmaxf(fmaxf(b.x, b.y), fmaxf(b.z, b.w)));
    #pragma unroll
    for (int o = 16; o > 0; o >>= 1)
        m = fmaxf(m, __shfl_xor_sync(0xffffffffu, m, o));

    __shared__ float sm_[8], ss[8];
    if ((tid & 31) == 0) sm_[tid >> 5] = m;
    __syncthreads();
    m = sm_[0];
    #pragma unroll
    for (int w = 1; w < 8; w++) m = fmaxf(m, sm_[w]);

    a.x = expf(a.x - m); a.y = expf(a.y - m); a.z = expf(a.z - m); a.w = expf(a.w - m);
    b.x = expf(b.x - m); b.y = expf(b.y - m); b.z = expf(b.z - m); b.w = expf(b.w - m);

    float s = a.x + a.y + a.z + a.w + b.x + b.y + b.z + b.w;
    #pragma unroll
    for (int o = 16; o > 0; o >>= 1)
        s += __shfl_xor_sync(0xffffffffu, s, o);
    if ((tid & 31) == 0) ss[tid >> 5] = s;
    __syncthreads();
    s = ss[0];
    #pragma unroll
    for (int w = 1; w < 8; w++) s += ss[w];

    const float inv = 1.0f / s;
    a.x *= inv; a.y *= inv; a.z *= inv; a.w *= inv;
    b.x *= inv; b.y *= inv; b.z *= inv; b.w *= inv;
    ((float4*)p)[tid]       = a;
    ((float4*)p)[tid + 256] = b;
}

// ---------------------------------------------------------------------------
// AV split-K x2 (R8): grid(16, 2, 32). BM=128, BN=64, BK=32, 2-stage.
// ---------------------------------------------------------------------------
#define AVA_BUF (128 * 36)
#define AVV_BUF (32 * 68)
#define AVSM ((2 * AVA_BUF + 2 * AVV_BUF) * 4)   // 54272 B

__device__ __forceinline__ void load_av_A(float* dst, const float* Ab, int tid) {
    const int ar = tid >> 1, ac = (tid & 1) * 16;
    const float* gp = Ab + (size_t)ar * SEQ + ac;
    float* sp = dst + ar * 36 + ac;
    cpa16(sp + 0,  gp + 0);
    cpa16(sp + 4,  gp + 4);
    cpa16(sp + 8,  gp + 8);
    cpa16(sp + 12, gp + 12);
}
__device__ __forceinline__ void load_av_V(float* dst, const float* Vb, int tid) {
    const int vr = tid >> 4, vc = (tid & 15) * 4;
    cpa16(&dst[vr * 68 + vc],        &Vb[(size_t)vr * E3 + vc]);
    cpa16(&dst[(vr + 16) * 68 + vc], &Vb[(size_t)(vr + 16) * E3 + vc]);
}

__global__ __launch_bounds__(256) void av_w(
    const float* __restrict__ attn, const float* __restrict__ qkv,
    float* __restrict__ ctx0, float* __restrict__ ctx1)
{
    extern __shared__ float sm[];
    float* As = sm;                    // 2 x [128][36]
    float* Vs = sm + 2 * AVA_BUF;      // 2 x [32][68]

    const int bh = blockIdx.z, b = bh >> 4, h = bh & 15;
    const int i0 = blockIdx.x * 128;
    const int half = blockIdx.y;
    const int kbase = half * (SEQ / 2);
    float* ctx = half ? ctx1 : ctx0;

    const float* Ag = attn + ((size_t)bh * SEQ + i0) * SEQ + kbase;
    const float* Vg = qkv + (size_t)b * SEQ * E3 + (size_t)kbase * E3 + h * 192 + 128;

    const int tid = threadIdx.x;
    const int w = tid >> 5;
    const int wr = w >> 1, wc = w & 1;

    FragC acc[2][2];
    #pragma unroll
    for (int i = 0; i < 2; i++)
        #pragma unroll
        for (int j = 0; j < 2; j++) wmma::fill_fragment(acc[i][j], 0.f);

    load_av_A(As, Ag, tid);
    load_av_V(Vs, Vg, tid);
    CP_COMMIT();

    const int nk = (SEQ / 2) / 32;  // 32
    for (int kt = 0; kt < nk; kt++) {
        const int cur = kt & 1;
        if (kt + 1 < nk) {
            const int k0 = (kt + 1) * 32;
            load_av_A(As + (cur ^ 1) * AVA_BUF, Ag + k0, tid);
            load_av_V(Vs + (cur ^ 1) * AVV_BUF, Vg + (size_t)k0 * E3, tid);
            CP_COMMIT();
            CP_WAIT(1);
        } else {
            CP_WAIT(0);
        }
        __syncthreads();

        const float* Ac = As + cur * AVA_BUF;
        const float* Vc = Vs + cur * AVV_BUF;
        #pragma unroll
        for (int kk = 0; kk < 32; kk += 8) {
            FragA a[2];
            FragBR bf[2];
            #pragma unroll
            for (int i = 0; i < 2; i++) {
                wmma::load_matrix_sync(a[i], &Ac[(wr * 32 + i * 16) * 36 + kk], 36);
                to_tf32(a[i]);
            }
            #pragma unroll
            for (int j = 0; j < 2; j++) {
                wmma::load_matrix_sync(bf[j], &Vc[kk * 68 + wc * 32 + j * 16], 68);
                to_tf32(bf[j]);
            }
            #pragma unroll
            for (int i = 0; i < 2; i++)
                #pragma unroll
                for (int j = 0; j < 2; j++)
                    wmma::mma_sync(acc[i][j], a[i], bf[j], acc[i][j]);
        }
        __syncthreads();
    }

    #pragma unroll
    for (int i = 0; i < 2; i++) {
        const int q = i0 + wr * 32 + i * 16;
        #pragma unroll
        for (int j = 0; j < 2; j++)
            wmma::store_matrix_sync(
                &ctx[((size_t)(b * SEQ + q)) * EMB + h * HDIM + wc * 32 + j * 16],
                acc[i][j], EMB, wmma::mem_row_major);
    }
}

// ---------------------------------------------------------------------------
// Combine split-K partials: ctx = ctx0 + ctx1 (float4)
// ---------------------------------------------------------------------------
__global__ __launch_bounds__(256) void combine_ctx(
    const float* __restrict__ c0, const float* __restrict__ c1,
    float* __restrict__ ctx)
{
    const size_t i = ((size_t)blockIdx.x * 256 + threadIdx.x) * 4;
    float4 a = *(const float4*)(c0 + i);
    float4 b = *(const float4*)(c1 + i);
    a.x += b.x; a.y += b.y; a.z += b.z; a.w += b.w;
    *(float4*)(ctx + i) = a;
}

// ---------------------------------------------------------------------------
extern "C" void kernel_launch(void* const* d_in, const int* in_sizes, int n_in,
                              void* d_out, int out_size)
{
    const float* x    = (const float*)d_in[0];
    const float* Wqkv = (const float*)d_in[1];
    const float* bqkv = (const float*)d_in[2];
    const float* Wout = (const float*)d_in[3];
    const float* bout = (const float*)d_in[4];
    float* out = (float*)d_out;

    const long long OUT_ELEMS  = (long long)BATCH * SEQ * EMB;
    const long long ATTN_ELEMS = (long long)BATCH * NHEAD * SEQ * SEQ;

    float *qkv, *ctx, *ctx0, *ctx1, *attn;
    cudaGetSymbolAddress((void**)&qkv,  g_qkv);
    cudaGetSymbolAddress((void**)&ctx,  g_ctx);
    cudaGetSymbolAddress((void**)&ctx0, g_ctx0);
    cudaGetSymbolAddress((void**)&ctx1, g_ctx1);
    if ((long long)out_size >= OUT_ELEMS + ATTN_ELEMS) {
        attn = out + OUT_ELEMS;
    } else {
        cudaGetSymbolAddress((void**)&attn, g_attn);
    }

    cudaFuncSetAttribute(gemm_bias_w, cudaFuncAttributeMaxDynamicSharedMemorySize, GSM);
    cudaFuncSetAttribute(scores_w,    cudaFuncAttributeMaxDynamicSharedMemorySize, SSM);
    cudaFuncSetAttribute(av_w,        cudaFuncAttributeMaxDynamicSharedMemorySize, AVSM);

    const int M = BATCH * SEQ;  // 4096

    // 1) QKV projection
    gemm_bias_w<<<dim3(E3 / 128, M / 128), 256, GSM>>>(x, Wqkv, bqkv, qkv, EMB, E3);

    // 2) Raw scores (QK^T)
    scores_w<<<dim3(SEQ / 128, SEQ / 128, BATCH * NHEAD), 256, SSM>>>(qkv, attn);

    // 3) Softmax with fused scale + ALiBi
    softmax_kernel<<<BATCH * NHEAD * SEQ, 256>>>(attn);

    // 4) AV (split-K x2) + combine
    av_w<<<dim3(SEQ / 128, 2, BATCH * NHEAD), 256, AVSM>>>(attn, qkv, ctx0, ctx1);
    combine_ctx<<<(int)(OUT_ELEMS / 4 / 256), 256>>>(ctx0, ctx1, ctx);

    // 5) Output projection
    gemm_bias_w<<<dim3(EMB / 128, M / 128), 256, GSM>>>(ctx, Wout, bout, out, EMB, EMB);
}